// round 16
// baseline (speedup 1.0000x reference)
#include <cuda_runtime.h>
#include <cuda_fp16.h>
#include <cstdint>

#define B_  2
#define T_  2048
#define D_  1024
#define F_  4096
#define H_  8
#define DH_ 128
#define M_  (B_*T_)              // 4096 rows
#define X_ELEMS (M_*D_)          // 4194304
#define QKV_N 3072

// ---------------- scratch (static device memory; no allocation at runtime) ----
static __device__ float g_xn [M_*D_];        // fp32 rmsnorm(x) (bgproj)
static __device__ float g_qkv[M_*QKV_N];     // fused q|k|v fp32
static __device__ float g_ba [M_*H_*2];

static __device__ __half g_xh[M_*D_];        // A operand fp16 (xn / yn)
static __device__ __half g_oh[M_*D_];        // deltanet out fp16
static __device__ __half g_hh[M_*F_];        // swiglu out fp16

static __device__ __half g_wqkv[QKV_N*D_];
static __device__ __half g_wo  [D_*D_];
static __device__ __half g_wgu [2*F_*D_];    // interleaved (gate,up) columns
static __device__ __half g_wd  [D_*F_];

__device__ __forceinline__ float silu_f(float x){ return x / (1.0f + expf(-x)); }
__device__ __forceinline__ float sigmoid_f(float x){ return 1.0f / (1.0f + expf(-x)); }

__device__ __forceinline__ uint32_t smem_u32(const void* p) {
    uint32_t a;
    asm("{ .reg .u64 t; cvta.to.shared.u64 t, %1; cvt.u32.u64 %0, t; }" : "=r"(a) : "l"(p));
    return a;
}

// ============================ elementwise / prep kernels ======================
// rmsnorm row of 1024 -> fp16 (+ optional fp32)
__global__ __launch_bounds__(256) void rmsnorm_h_k(const float* __restrict__ in,
                                                   __half* __restrict__ oh,
                                                   float* __restrict__ of)
{
    int row = blockIdx.x;
    int tid = threadIdx.x;
    const float4* ip = (const float4*)(in + (size_t)row * D_);
    float4 v = ip[tid];
    float ss = v.x*v.x + v.y*v.y + v.z*v.z + v.w*v.w;
    #pragma unroll
    for (int m = 16; m > 0; m >>= 1) ss += __shfl_xor_sync(0xffffffffu, ss, m);
    __shared__ float sred[8];
    if ((tid & 31) == 0) sred[tid >> 5] = ss;
    __syncthreads();
    float tot = 0.f;
    #pragma unroll
    for (int i = 0; i < 8; i++) tot += sred[i];
    float sc = rsqrtf(tot * (1.0f / D_) + 1e-6f);
    float4 o; o.x = v.x*sc; o.y = v.y*sc; o.z = v.z*sc; o.w = v.w*sc;
    __half2 h0 = __floats2half2_rn(o.x, o.y);
    __half2 h1 = __floats2half2_rn(o.z, o.w);
    size_t base2 = ((size_t)row * D_) / 2 + tid*2;
    ((__half2*)oh)[base2]   = h0;
    ((__half2*)oh)[base2+1] = h1;
    if (of) ((float4*)(of + (size_t)row * D_))[tid] = o;
}

// transpose [R][Cc] fp32 -> out[(c*cmul+cadd)][R] fp16
__global__ __launch_bounds__(256) void tsplit_k(const float* __restrict__ in,
                                                __half* __restrict__ oh,
                                                int R, int Cc, int cmul, int cadd)
{
    __shared__ float t[32][33];
    int tx = threadIdx.x & 31, ty = threadIdx.x >> 5;   // 32x8
    int c0 = blockIdx.x * 32, r0 = blockIdx.y * 32;
    #pragma unroll
    for (int i = 0; i < 4; i++)
        t[ty + i*8][tx] = in[(size_t)(r0 + ty + i*8) * Cc + c0 + tx];
    __syncthreads();
    #pragma unroll
    for (int i = 0; i < 4; i++) {
        int oc = ty + i*8;
        size_t oi = ((size_t)(c0 + oc) * cmul + cadd) * R + r0 + tx;
        oh[oi] = __float2half(t[tx][oc]);
    }
}

// merged qkv transpose: z selects wq/wk/wv; out col offset z*1024
__global__ __launch_bounds__(256) void tsplit3_k(const float* __restrict__ wq,
                                                 const float* __restrict__ wk,
                                                 const float* __restrict__ wv,
                                                 __half* __restrict__ oh)
{
    __shared__ float t[32][33];
    const float* in = (blockIdx.z == 0) ? wq : (blockIdx.z == 1) ? wk : wv;
    int cadd = blockIdx.z * 1024;
    int tx = threadIdx.x & 31, ty = threadIdx.x >> 5;   // 32x8
    int c0 = blockIdx.x * 32, r0 = blockIdx.y * 32;
    #pragma unroll
    for (int i = 0; i < 4; i++)
        t[ty + i*8][tx] = in[(size_t)(r0 + ty + i*8) * D_ + c0 + tx];
    __syncthreads();
    #pragma unroll
    for (int i = 0; i < 4; i++) {
        int oc = ty + i*8;
        size_t oi = (size_t)(c0 + oc + cadd) * D_ + r0 + tx;
        oh[oi] = __float2half(t[tx][oc]);
    }
}

// silu (+L2 norm for q,k heads) over fused qkv rows of 128
__global__ __launch_bounds__(256) void silul2_qkv_k(float* __restrict__ qkv)
{
    int r = blockIdx.x * 8 + (threadIdx.x >> 5);   // row-of-128 index, 0..M*24-1
    int lane = threadIdx.x & 31;
    int m = r / 24, sec = r % 24;
    float4* p = (float4*)(qkv + (size_t)m * QKV_N + sec * 128) + lane;
    float4 x = *p;
    float4 s;
    s.x = silu_f(x.x); s.y = silu_f(x.y); s.z = silu_f(x.z); s.w = silu_f(x.w);
    if (sec < 16) {   // q and k heads get L2 norm
        float ss = s.x*s.x + s.y*s.y + s.z*s.z + s.w*s.w;
        #pragma unroll
        for (int m2 = 16; m2 > 0; m2 >>= 1) ss += __shfl_xor_sync(0xffffffffu, ss, m2);
        float sc = rsqrtf(ss + 1e-6f);
        s.x *= sc; s.y *= sc; s.z *= sc; s.w *= sc;
    }
    *p = s;
}

// ============================ mma.sync fp16 GEMM ==============================
// C[M,N] = (addend?) + A[M,K] @ Bt[N,K]^T, fp16 in, fp32 accumulate.
// Tile 128x128, BK=64, 128 threads (4 warps, warp tile 64x64), 3-stage cp.async,
// 2 CTAs/SM, ONE barrier per kt. K-accumulation order identical to BK=32 version.
// EPI: 0 = write C fp32; 1 = C = addend + acc; 2 = swiglu -> fp16.
#define RSB   144                     // smem row stride bytes (128 data + 16 pad)
#define TILE_B (128*RSB)              // 18432 B per operand tile
#define STAGE_B (TILE_B*2)            // 36864 B per stage (A,B)
#define HG_SMEM (STAGE_B*3)           // 110592 B

__device__ __forceinline__ void ldsm_x4(uint32_t& r0, uint32_t& r1,
                                        uint32_t& r2, uint32_t& r3, uint32_t a) {
    asm volatile("ldmatrix.sync.aligned.m8n8.x4.shared.b16 {%0,%1,%2,%3}, [%4];"
                 : "=r"(r0), "=r"(r1), "=r"(r2), "=r"(r3) : "r"(a));
}
__device__ __forceinline__ void mma16816(float& d0, float& d1, float& d2, float& d3,
                                         uint32_t a0, uint32_t a1, uint32_t a2, uint32_t a3,
                                         uint32_t b0, uint32_t b1) {
    asm volatile("mma.sync.aligned.m16n8k16.row.col.f32.f16.f16.f32 "
                 "{%0,%1,%2,%3}, {%4,%5,%6,%7}, {%8,%9}, {%0,%1,%2,%3};"
                 : "+f"(d0), "+f"(d1), "+f"(d2), "+f"(d3)
                 : "r"(a0), "r"(a1), "r"(a2), "r"(a3), "r"(b0), "r"(b1));
}
__device__ __forceinline__ void cp16(uint32_t s, const void* g) {
    asm volatile("cp.async.cg.shared.global [%0], [%1], 16;" :: "r"(s), "l"(g));
}

template<int EPI>
__global__ __launch_bounds__(128, 2) void hgemm_k(
    const __half* __restrict__ Ah, const __half* __restrict__ Bh,
    const float* __restrict__ addend, float* __restrict__ C,
    __half* __restrict__ Hh,
    int M, int N, int K)
{
    extern __shared__ char smem[];
    uint32_t S0 = smem_u32(smem);

    int tid = threadIdx.x;
    int wid = tid >> 5, lane = tid & 31;
    int m0 = blockIdx.y << 7, n0 = blockIdx.x << 7;

    int seg = tid & 7, rw = tid >> 3;        // seg 0..7, rw 0..15
    const __half* gA[2] = { Ah, Bh };
    int rbase[2] = { m0, n0 };

    int NK = K >> 6;

    // prefetch stages 0,1 (16 cp16 per thread per stage)
    #pragma unroll
    for (int st = 0; st < 2; st++) {
        uint32_t sb = S0 + st * STAGE_B;
        int k0 = st << 6;
        #pragma unroll
        for (int ten = 0; ten < 2; ten++) {
            #pragma unroll
            for (int r8 = 0; r8 < 8; r8++) {
                int row = rw + r8 * 16;
                const __half* G = gA[ten] + (size_t)(rbase[ten] + row) * K + k0 + seg * 8;
                cp16(sb + ten * TILE_B + row * RSB + seg * 16, G);
            }
        }
        asm volatile("cp.async.commit_group;");
    }

    int wm = wid >> 1, wn = wid & 1;
    int m_off = wm * 64, n_off = wn * 64;

    uint32_t a_lo = (uint32_t)((lane & 15) * RSB + (lane >> 4) * 16);
    uint32_t b_lo = (uint32_t)(((lane & 7) + ((lane >> 4) << 3)) * RSB + (((lane >> 3) & 1) << 4));

    float acc[4][8][4];
    #pragma unroll
    for (int i = 0; i < 4; i++)
        #pragma unroll
        for (int j = 0; j < 8; j++)
            #pragma unroll
            for (int r = 0; r < 4; r++) acc[i][j][r] = 0.f;

    for (int kt = 0; kt < NK; kt++) {
        if (kt + 1 < NK) asm volatile("cp.async.wait_group 1;");
        else             asm volatile("cp.async.wait_group 0;");
        __syncthreads();

        if (kt + 2 < NK) {
            int st = (kt + 2) % 3;
            uint32_t sb = S0 + st * STAGE_B;
            int k0 = (kt + 2) << 6;
            #pragma unroll
            for (int ten = 0; ten < 2; ten++) {
                #pragma unroll
                for (int r8 = 0; r8 < 8; r8++) {
                    int row = rw + r8 * 16;
                    const __half* G = gA[ten] + (size_t)(rbase[ten] + row) * K + k0 + seg * 8;
                    cp16(sb + ten * TILE_B + row * RSB + seg * 16, G);
                }
            }
            asm volatile("cp.async.commit_group;");
        }

        uint32_t base = S0 + (kt % 3) * STAGE_B;
        uint32_t tA = base, tB = base + TILE_B;

        #pragma unroll
        for (int kkp = 0; kkp < 2; kkp++) {
            uint32_t ah[2][4][4];
            uint32_t bh[2][8][2];
            #pragma unroll
            for (int kh = 0; kh < 2; kh++) {
                uint32_t koff = (uint32_t)((kkp * 2 + kh) * 32);
                #pragma unroll
                for (int mi = 0; mi < 4; mi++) {
                    uint32_t off = (uint32_t)((m_off + mi*16) * RSB) + koff + a_lo;
                    ldsm_x4(ah[kh][mi][0], ah[kh][mi][1], ah[kh][mi][2], ah[kh][mi][3], tA + off);
                }
                #pragma unroll
                for (int nj = 0; nj < 4; nj++) {
                    uint32_t off = (uint32_t)((n_off + nj*16) * RSB) + koff + b_lo;
                    uint32_t r0, r1, r2, r3;
                    ldsm_x4(r0, r1, r2, r3, tB + off);
                    bh[kh][nj*2][0] = r0; bh[kh][nj*2][1] = r1;
                    bh[kh][nj*2+1][0] = r2; bh[kh][nj*2+1][1] = r3;
                }
            }
            #pragma unroll
            for (int kh = 0; kh < 2; kh++)
                #pragma unroll
                for (int mi = 0; mi < 4; mi++)
                    #pragma unroll
                    for (int ni = 0; ni < 8; ni++)
                        mma16816(acc[mi][ni][0], acc[mi][ni][1], acc[mi][ni][2], acc[mi][ni][3],
                                 ah[kh][mi][0], ah[kh][mi][1], ah[kh][mi][2], ah[kh][mi][3],
                                 bh[kh][ni][0], bh[kh][ni][1]);
        }
    }

    // epilogue
    int rbase_m = m0 + m_off + (lane >> 2);
    #pragma unroll
    for (int mi = 0; mi < 4; mi++) {
        #pragma unroll
        for (int ni = 0; ni < 8; ni++) {
            int row = rbase_m + mi * 16;
            if (EPI == 2) {
                int c = n_off + ni*8 + (lane & 3) * 2;
                int j = (n0 + c) >> 1;
                int hw = N >> 1;
                float h1v = silu_f(acc[mi][ni][0]) * acc[mi][ni][1];
                float h2v = silu_f(acc[mi][ni][2]) * acc[mi][ni][3];
                Hh[(size_t)row * hw + j]     = __float2half(h1v);
                Hh[(size_t)(row+8) * hw + j] = __float2half(h2v);
            } else {
                int col = n0 + n_off + ni*8 + (lane & 3) * 2;
                float2 v0 = { acc[mi][ni][0], acc[mi][ni][1] };
                float2 v1 = { acc[mi][ni][2], acc[mi][ni][3] };
                if (EPI == 1) {
                    float2 a0 = *(const float2*)(addend + (size_t)row * N + col);
                    float2 a1 = *(const float2*)(addend + (size_t)(row + 8) * N + col);
                    v0.x += a0.x; v0.y += a0.y; v1.x += a1.x; v1.y += a1.y;
                }
                *(float2*)(C + (size_t)row * N + col) = v0;
                *(float2*)(C + (size_t)(row + 8) * N + col) = v1;
            }
        }
    }
}

// ---------------- beta/alpha projection (smem-cached weights) ------------------
// 128 blocks x 32 rows; 256 threads; w16[1024][16] staged in 64KB dynamic smem.
// Per warp-row: lane=(col 0..15, half 0..1); 512 broadcast x-loads + smem FMA;
// shfl to merge halves; sigmoid; store.
#define BG_SMEM (D_*16*4)   // 65536 B
__global__ __launch_bounds__(256) void bgproj2_k(const float* __restrict__ xn,
                                                 const float* __restrict__ wb,
                                                 const float* __restrict__ wg,
                                                 float* __restrict__ ba)
{
    extern __shared__ float w16[];   // [1024][16]: cols 0-7 beta, 8-15 alpha
    int tid = threadIdx.x;
    for (int i = tid; i < D_; i += 256) {
        float4 b0 = *(const float4*)(wb + (size_t)i*8);
        float4 b1 = *(const float4*)(wb + (size_t)i*8 + 4);
        float4 g0 = *(const float4*)(wg + (size_t)i*8);
        float4 g1 = *(const float4*)(wg + (size_t)i*8 + 4);
        float* w = w16 + i*16;
        w[0]=b0.x;  w[1]=b0.y;  w[2]=b0.z;  w[3]=b0.w;
        w[4]=b1.x;  w[5]=b1.y;  w[6]=b1.z;  w[7]=b1.w;
        w[8]=g0.x;  w[9]=g0.y;  w[10]=g0.z; w[11]=g0.w;
        w[12]=g1.x; w[13]=g1.y; w[14]=g1.z; w[15]=g1.w;
    }
    __syncthreads();

    int warp = tid >> 5, lane = tid & 31;
    int col = lane & 15, half = lane >> 4;
    int rowbase = blockIdx.x * 32;

    for (int r = warp; r < 32; r += 8) {
        int row = rowbase + r;
        const float* xr = xn + (size_t)row * D_;
        float acc = 0.f;
        #pragma unroll 8
        for (int j = 0; j < 512; j++) {
            int e = half + 2*j;
            acc += xr[e] * w16[e*16 + col];
        }
        acc += __shfl_xor_sync(0xffffffffu, acc, 16);
        if (half == 0) {
            float val = sigmoid_f(acc);
            ba[(size_t)row*16 + ((col & 7)*2 + (col >> 3))] = val;
        }
    }
}

// ---------------- gated DeltaNet recurrence -----------------------------------
__global__ __launch_bounds__(128) void deltarec_k(const float* __restrict__ qkv,
                                                  const float* __restrict__ ba,
                                                  const float* __restrict__ s0,
                                                  __half* __restrict__ oh,
                                                  float* __restrict__ sout)
{
    int b = blockIdx.z, h = blockIdx.y, chunk = blockIdx.x;
    int tid = threadIdx.x;
    int warp = tid >> 5, lane = tid & 31;
    int grp = lane >> 4;
    int idx = lane & 15;
    int col = chunk*8 + warp*2 + grp;
    int r0  = idx * 8;

    float s[8];
    {
        const float* sp = s0 + (((size_t)(b*H_ + h)*DH_) + r0)*DH_ + col;
        #pragma unroll
        for (int i = 0; i < 8; i++) s[i] = sp[(size_t)i * DH_];
    }

    const float* base = qkv + (size_t)b * T_ * QKV_N + h * DH_;
    const float* qp  = base + r0;
    const float* kp  = base + 1024 + r0;
    const float* vp  = base + 2048 + col;
    const float* bap = ba + ((size_t)b * T_) * (H_*2) + h*2;
    size_t ooff = (size_t)b * T_ * D_ + (size_t)h * DH_ + col;

    float4 k0 = *(const float4*)(kp);
    float4 k1 = *(const float4*)(kp + 4);
    float4 q0 = *(const float4*)(qp);
    float4 q1 = *(const float4*)(qp + 4);
    float vv = *vp;
    float bb = bap[0];
    float aa = bap[1];

    for (int t = 0; t < T_; t++) {
        int tn = (t + 1 < T_) ? t + 1 : t;
        float4 nk0 = *(const float4*)(kp + (size_t)tn*QKV_N);
        float4 nk1 = *(const float4*)(kp + (size_t)tn*QKV_N + 4);
        float4 nq0 = *(const float4*)(qp + (size_t)tn*QKV_N);
        float4 nq1 = *(const float4*)(qp + (size_t)tn*QKV_N + 4);
        float nvv  = vp [(size_t)tn*QKV_N];
        float nbb  = bap[(size_t)tn*16];
        float naa  = bap[(size_t)tn*16 + 1];

        float kr[8] = {k0.x,k0.y,k0.z,k0.w,k1.x,k1.y,k1.z,k1.w};
        float qr[8] = {q0.x,q0.y,q0.z,q0.w,q1.x,q1.y,q1.z,q1.w};

        float pred = 0.f, po = 0.f, qk = 0.f;
        #pragma unroll
        for (int i = 0; i < 8; i++) {
            float sv = s[i] * aa;
            s[i] = sv;
            pred += kr[i] * sv;
            po   += qr[i] * sv;
            qk   += kr[i] * qr[i];
        }
        #pragma unroll
        for (int m = 1; m < 16; m <<= 1) {
            pred += __shfl_xor_sync(0xffffffffu, pred, m);
            po   += __shfl_xor_sync(0xffffffffu, po,   m);
            qk   += __shfl_xor_sync(0xffffffffu, qk,   m);
        }
        float dv = bb * (vv - pred);
        float ov = po + qk * dv;
        #pragma unroll
        for (int i = 0; i < 8; i++) s[i] += kr[i] * dv;

        if (idx == 0) oh[ooff + (size_t)t*D_] = __float2half(ov);

        k0 = nk0; k1 = nk1; q0 = nq0; q1 = nq1;
        vv = nvv; bb = nbb; aa = naa;
    }

    float* sp = sout + (((size_t)(b*H_ + h)*DH_) + r0)*DH_ + col;
    #pragma unroll
    for (int i = 0; i < 8; i++) sp[(size_t)i * DH_] = s[i];
}

// ---------------- launcher -----------------------------------------------------
struct Ptrs {
    float *xn, *qkv, *ba;
    __half *xh, *oh, *hh;
    __half *wqkv, *wo, *wgu, *wd;
    bool init = false;
};
static Ptrs P;

extern "C" void kernel_launch(void* const* d_in, const int* in_sizes, int n_in,
                              void* d_out, int out_size)
{
    const float* x   = (const float*)d_in[0];
    const float* st0 = (const float*)d_in[1];
    const float* wq  = (const float*)d_in[2];
    const float* wk  = (const float*)d_in[3];
    const float* wv  = (const float*)d_in[4];
    const float* wb  = (const float*)d_in[5];
    const float* wg  = (const float*)d_in[6];
    const float* wo  = (const float*)d_in[7];
    const float* wgate = (const float*)d_in[8];
    const float* wup   = (const float*)d_in[9];
    const float* wdown = (const float*)d_in[10];

    float* out = (float*)d_out;   // [x (4194304) | new_state (262144)]
    float* y   = out;
    float* stO = out + X_ELEMS;

    if (!P.init) {
        cudaGetSymbolAddress((void**)&P.xn,  g_xn);
        cudaGetSymbolAddress((void**)&P.qkv, g_qkv);
        cudaGetSymbolAddress((void**)&P.ba,  g_ba);
        cudaGetSymbolAddress((void**)&P.xh,  g_xh);
        cudaGetSymbolAddress((void**)&P.oh,  g_oh);
        cudaGetSymbolAddress((void**)&P.hh,  g_hh);
        cudaGetSymbolAddress((void**)&P.wqkv, g_wqkv);
        cudaGetSymbolAddress((void**)&P.wo,   g_wo);
        cudaGetSymbolAddress((void**)&P.wgu,  g_wgu);
        cudaGetSymbolAddress((void**)&P.wd,   g_wd);
        cudaFuncSetAttribute(hgemm_k<0>, cudaFuncAttributeMaxDynamicSharedMemorySize, HG_SMEM);
        cudaFuncSetAttribute(hgemm_k<1>, cudaFuncAttributeMaxDynamicSharedMemorySize, HG_SMEM);
        cudaFuncSetAttribute(hgemm_k<2>, cudaFuncAttributeMaxDynamicSharedMemorySize, HG_SMEM);
        cudaFuncSetAttribute(bgproj2_k,  cudaFuncAttributeMaxDynamicSharedMemorySize, BG_SMEM);
        P.init = true;
    }

    // [1] merged qkv weight transpose -> fp16 [3072][1024]
    tsplit3_k<<<dim3(D_/32, D_/32, 3), 256>>>(wq, wk, wv, P.wqkv);

    // [2] xn = rmsnorm(x) -> fp16 + fp32 (for bgproj)
    rmsnorm_h_k<<<M_, 256>>>(x, P.xh, P.xn);

    // [3] fused qkv projection
    hgemm_k<0><<<dim3(QKV_N/128, M_/128), 128, HG_SMEM>>>(
        P.xh, P.wqkv, nullptr, P.qkv, nullptr, M_, QKV_N, D_);

    // [4] beta/alpha projection (smem-cached weights)
    bgproj2_k<<<M_/32, 256, BG_SMEM>>>(P.xn, wb, wg, P.ba);

    // [5] silu + per-head L2 norm (q,k); silu (v) — fused over qkv
    silul2_qkv_k<<<(M_*24)/8, 256>>>(P.qkv);

    // [6] recurrence -> o (fp16), final state
    deltarec_k<<<dim3(16, H_, B_), 128>>>(P.qkv, P.ba, st0, P.oh, stO);

    // [7] wo transpose; [8] y = x + o @ wo
    tsplit_k<<<dim3(D_/32, D_/32), 256>>>(wo, P.wo, D_, D_, 1, 0);
    hgemm_k<1><<<dim3(D_/128, M_/128), 128, HG_SMEM>>>(
        P.oh, P.wo, x, y, nullptr, M_, D_, D_);

    // [9] yn = rmsnorm(y) -> fp16
    rmsnorm_h_k<<<M_, 256>>>(y, P.xh, nullptr);

    // [10-11] gate/up transposes; [12] fused gate/up GEMM with swiglu epilogue
    tsplit_k<<<dim3(F_/32, D_/32), 256>>>(wgate, P.wgu, D_, F_, 2, 0);
    tsplit_k<<<dim3(F_/32, D_/32), 256>>>(wup,   P.wgu, D_, F_, 2, 1);
    hgemm_k<2><<<dim3(2*F_/128, M_/128), 128, HG_SMEM>>>(
        P.xh, P.wgu, nullptr, nullptr, P.hh, M_, 2*F_, D_);

    // [13] wdown transpose; [14] out = y + h @ w_down
    tsplit_k<<<dim3(D_/32, F_/32), 256>>>(wdown, P.wd, F_, D_, 1, 0);
    hgemm_k<1><<<dim3(D_/128, M_/128), 128, HG_SMEM>>>(
        P.hh, P.wd, y, y, nullptr, M_, D_, F_);
}

// round 17
// speedup vs baseline: 1.0170x; 1.0170x over previous
#include <cuda_runtime.h>
#include <cuda_fp16.h>
#include <cstdint>

#define B_  2
#define T_  2048
#define D_  1024
#define F_  4096
#define H_  8
#define DH_ 128
#define M_  (B_*T_)              // 4096 rows
#define X_ELEMS (M_*D_)          // 4194304
#define QKV_N 3072

// ---------------- scratch (static device memory; no allocation at runtime) ----
static __device__ float g_xn [M_*D_];        // fp32 rmsnorm(x) (bgproj)
static __device__ float g_qkv[M_*QKV_N];     // fused q|k|v fp32
static __device__ float g_ba [M_*H_*2];

static __device__ __half g_xh[M_*D_];        // A operand fp16 (xn / yn)
static __device__ __half g_oh[M_*D_];        // deltanet out fp16
static __device__ __half g_hh[M_*F_];        // swiglu out fp16

static __device__ __half g_wqkv[QKV_N*D_];
static __device__ __half g_wo  [D_*D_];
static __device__ __half g_wgu [2*F_*D_];    // interleaved (gate,up) columns
static __device__ __half g_wd  [D_*F_];

__device__ __forceinline__ float silu_f(float x){ return x / (1.0f + expf(-x)); }
__device__ __forceinline__ float sigmoid_f(float x){ return 1.0f / (1.0f + expf(-x)); }

__device__ __forceinline__ uint32_t smem_u32(const void* p) {
    uint32_t a;
    asm("{ .reg .u64 t; cvta.to.shared.u64 t, %1; cvt.u32.u64 %0, t; }" : "=r"(a) : "l"(p));
    return a;
}

// ============================ elementwise / prep kernels ======================
// rmsnorm row of 1024 -> fp16 (+ optional fp32)
__global__ __launch_bounds__(256) void rmsnorm_h_k(const float* __restrict__ in,
                                                   __half* __restrict__ oh,
                                                   float* __restrict__ of)
{
    int row = blockIdx.x;
    int tid = threadIdx.x;
    const float4* ip = (const float4*)(in + (size_t)row * D_);
    float4 v = ip[tid];
    float ss = v.x*v.x + v.y*v.y + v.z*v.z + v.w*v.w;
    #pragma unroll
    for (int m = 16; m > 0; m >>= 1) ss += __shfl_xor_sync(0xffffffffu, ss, m);
    __shared__ float sred[8];
    if ((tid & 31) == 0) sred[tid >> 5] = ss;
    __syncthreads();
    float tot = 0.f;
    #pragma unroll
    for (int i = 0; i < 8; i++) tot += sred[i];
    float sc = rsqrtf(tot * (1.0f / D_) + 1e-6f);
    float4 o; o.x = v.x*sc; o.y = v.y*sc; o.z = v.z*sc; o.w = v.w*sc;
    __half2 h0 = __floats2half2_rn(o.x, o.y);
    __half2 h1 = __floats2half2_rn(o.z, o.w);
    size_t base2 = ((size_t)row * D_) / 2 + tid*2;
    ((__half2*)oh)[base2]   = h0;
    ((__half2*)oh)[base2+1] = h1;
    if (of) ((float4*)(of + (size_t)row * D_))[tid] = o;
}

// transpose [R][Cc] fp32 -> out[(c*cmul+cadd)][R] fp16
__global__ __launch_bounds__(256) void tsplit_k(const float* __restrict__ in,
                                                __half* __restrict__ oh,
                                                int R, int Cc, int cmul, int cadd)
{
    __shared__ float t[32][33];
    int tx = threadIdx.x & 31, ty = threadIdx.x >> 5;   // 32x8
    int c0 = blockIdx.x * 32, r0 = blockIdx.y * 32;
    #pragma unroll
    for (int i = 0; i < 4; i++)
        t[ty + i*8][tx] = in[(size_t)(r0 + ty + i*8) * Cc + c0 + tx];
    __syncthreads();
    #pragma unroll
    for (int i = 0; i < 4; i++) {
        int oc = ty + i*8;
        size_t oi = ((size_t)(c0 + oc) * cmul + cadd) * R + r0 + tx;
        oh[oi] = __float2half(t[tx][oc]);
    }
}

// merged qkv transpose: z selects wq/wk/wv; out col offset z*1024
__global__ __launch_bounds__(256) void tsplit3_k(const float* __restrict__ wq,
                                                 const float* __restrict__ wk,
                                                 const float* __restrict__ wv,
                                                 __half* __restrict__ oh)
{
    __shared__ float t[32][33];
    const float* in = (blockIdx.z == 0) ? wq : (blockIdx.z == 1) ? wk : wv;
    int cadd = blockIdx.z * 1024;
    int tx = threadIdx.x & 31, ty = threadIdx.x >> 5;   // 32x8
    int c0 = blockIdx.x * 32, r0 = blockIdx.y * 32;
    #pragma unroll
    for (int i = 0; i < 4; i++)
        t[ty + i*8][tx] = in[(size_t)(r0 + ty + i*8) * D_ + c0 + tx];
    __syncthreads();
    #pragma unroll
    for (int i = 0; i < 4; i++) {
        int oc = ty + i*8;
        size_t oi = (size_t)(c0 + oc + cadd) * D_ + r0 + tx;
        oh[oi] = __float2half(t[tx][oc]);
    }
}

// silu (+L2 norm for q,k heads) over fused qkv rows of 128
__global__ __launch_bounds__(256) void silul2_qkv_k(float* __restrict__ qkv)
{
    int r = blockIdx.x * 8 + (threadIdx.x >> 5);   // row-of-128 index, 0..M*24-1
    int lane = threadIdx.x & 31;
    int m = r / 24, sec = r % 24;
    float4* p = (float4*)(qkv + (size_t)m * QKV_N + sec * 128) + lane;
    float4 x = *p;
    float4 s;
    s.x = silu_f(x.x); s.y = silu_f(x.y); s.z = silu_f(x.z); s.w = silu_f(x.w);
    if (sec < 16) {   // q and k heads get L2 norm
        float ss = s.x*s.x + s.y*s.y + s.z*s.z + s.w*s.w;
        #pragma unroll
        for (int m2 = 16; m2 > 0; m2 >>= 1) ss += __shfl_xor_sync(0xffffffffu, ss, m2);
        float sc = rsqrtf(ss + 1e-6f);
        s.x *= sc; s.y *= sc; s.z *= sc; s.w *= sc;
    }
    *p = s;
}

// ============================ mma.sync fp16 GEMM ==============================
// C[M,N] = (addend?) + A[M,K] @ Bt[N,K]^T, fp16 in, fp32 accumulate.
// Tile 128x128, BK=32, 128 threads (4 warps, warp tile 64x64), 4-stage cp.async,
// 2 CTAs/SM, ONE barrier per kt, fragments batch-loaded.   (proven R11 config)
// EPI: 0 = write C fp32; 1 = C = addend + acc; 2 = swiglu -> fp16.
#define TILE_B (128*80)               // 10240 B per operand tile
#define STAGE_B (TILE_B*2)            // 20480 B per stage (A,B)
#define HG_SMEM (STAGE_B*4)           // 81920 B

__device__ __forceinline__ void ldsm_x4(uint32_t& r0, uint32_t& r1,
                                        uint32_t& r2, uint32_t& r3, uint32_t a) {
    asm volatile("ldmatrix.sync.aligned.m8n8.x4.shared.b16 {%0,%1,%2,%3}, [%4];"
                 : "=r"(r0), "=r"(r1), "=r"(r2), "=r"(r3) : "r"(a));
}
__device__ __forceinline__ void mma16816(float& d0, float& d1, float& d2, float& d3,
                                         uint32_t a0, uint32_t a1, uint32_t a2, uint32_t a3,
                                         uint32_t b0, uint32_t b1) {
    asm volatile("mma.sync.aligned.m16n8k16.row.col.f32.f16.f16.f32 "
                 "{%0,%1,%2,%3}, {%4,%5,%6,%7}, {%8,%9}, {%0,%1,%2,%3};"
                 : "+f"(d0), "+f"(d1), "+f"(d2), "+f"(d3)
                 : "r"(a0), "r"(a1), "r"(a2), "r"(a3), "r"(b0), "r"(b1));
}
__device__ __forceinline__ void cp16(uint32_t s, const void* g) {
    asm volatile("cp.async.cg.shared.global [%0], [%1], 16;" :: "r"(s), "l"(g));
}

template<int EPI>
__global__ __launch_bounds__(128, 2) void hgemm_k(
    const __half* __restrict__ Ah, const __half* __restrict__ Bh,
    const float* __restrict__ addend, float* __restrict__ C,
    __half* __restrict__ Hh,
    int M, int N, int K)
{
    extern __shared__ char smem[];
    uint32_t S0 = smem_u32(smem);

    int tid = threadIdx.x;
    int wid = tid >> 5, lane = tid & 31;
    int m0 = blockIdx.y << 7, n0 = blockIdx.x << 7;

    int seg = tid & 3, rr = tid >> 2;        // rr 0..31
    const __half* gA[2] = { Ah, Bh };
    int rbase[2] = { m0, n0 };

    int NK = K >> 5;

    // prefetch stages 0..2 (8 cp16 per thread per stage)
    #pragma unroll
    for (int st = 0; st < 3; st++) {
        uint32_t sb = S0 + st * STAGE_B;
        int k0 = st << 5;
        #pragma unroll
        for (int ten = 0; ten < 2; ten++) {
            #pragma unroll
            for (int r4 = 0; r4 < 4; r4++) {
                int row = rr + r4 * 32;
                const __half* G = gA[ten] + (size_t)(rbase[ten] + row) * K + k0 + seg * 8;
                cp16(sb + ten * TILE_B + row * 80 + seg * 16, G);
            }
        }
        asm volatile("cp.async.commit_group;");
    }

    int wm = wid >> 1, wn = wid & 1;
    int m_off = wm * 64, n_off = wn * 64;

    uint32_t a_lo = (uint32_t)((lane & 15) * 80 + (lane >> 4) * 16);
    uint32_t b_lo = (uint32_t)(((lane & 7) + ((lane >> 4) << 3)) * 80 + (((lane >> 3) & 1) << 4));

    float acc[4][8][4];
    #pragma unroll
    for (int i = 0; i < 4; i++)
        #pragma unroll
        for (int j = 0; j < 8; j++)
            #pragma unroll
            for (int r = 0; r < 4; r++) acc[i][j][r] = 0.f;

    for (int kt = 0; kt < NK; kt++) {
        if      (kt + 2 < NK) asm volatile("cp.async.wait_group 2;");
        else if (kt + 1 < NK) asm volatile("cp.async.wait_group 1;");
        else                  asm volatile("cp.async.wait_group 0;");
        __syncthreads();

        if (kt + 3 < NK) {
            int st = (kt + 3) & 3;
            uint32_t sb = S0 + st * STAGE_B;
            int k0 = (kt + 3) << 5;
            #pragma unroll
            for (int ten = 0; ten < 2; ten++) {
                #pragma unroll
                for (int r4 = 0; r4 < 4; r4++) {
                    int row = rr + r4 * 32;
                    const __half* G = gA[ten] + (size_t)(rbase[ten] + row) * K + k0 + seg * 8;
                    cp16(sb + ten * TILE_B + row * 80 + seg * 16, G);
                }
            }
            asm volatile("cp.async.commit_group;");
        }

        uint32_t base = S0 + (kt & 3) * STAGE_B;
        uint32_t tA = base, tB = base + TILE_B;

        uint32_t ah[2][4][4];
        uint32_t bh[2][8][2];
        #pragma unroll
        for (int kk = 0; kk < 2; kk++) {
            uint32_t koff = (uint32_t)(kk * 32);
            #pragma unroll
            for (int mi = 0; mi < 4; mi++) {
                uint32_t off = (uint32_t)((m_off + mi*16) * 80) + koff + a_lo;
                ldsm_x4(ah[kk][mi][0], ah[kk][mi][1], ah[kk][mi][2], ah[kk][mi][3], tA + off);
            }
            #pragma unroll
            for (int nj = 0; nj < 4; nj++) {
                uint32_t off = (uint32_t)((n_off + nj*16) * 80) + koff + b_lo;
                uint32_t r0, r1, r2, r3;
                ldsm_x4(r0, r1, r2, r3, tB + off);
                bh[kk][nj*2][0] = r0; bh[kk][nj*2][1] = r1;
                bh[kk][nj*2+1][0] = r2; bh[kk][nj*2+1][1] = r3;
            }
        }
        #pragma unroll
        for (int kk = 0; kk < 2; kk++)
            #pragma unroll
            for (int mi = 0; mi < 4; mi++)
                #pragma unroll
                for (int ni = 0; ni < 8; ni++)
                    mma16816(acc[mi][ni][0], acc[mi][ni][1], acc[mi][ni][2], acc[mi][ni][3],
                             ah[kk][mi][0], ah[kk][mi][1], ah[kk][mi][2], ah[kk][mi][3],
                             bh[kk][ni][0], bh[kk][ni][1]);
    }

    // epilogue
    int rbase_m = m0 + m_off + (lane >> 2);
    #pragma unroll
    for (int mi = 0; mi < 4; mi++) {
        #pragma unroll
        for (int ni = 0; ni < 8; ni++) {
            int row = rbase_m + mi * 16;
            if (EPI == 2) {
                int c = n_off + ni*8 + (lane & 3) * 2;
                int j = (n0 + c) >> 1;
                int hw = N >> 1;
                float h1v = silu_f(acc[mi][ni][0]) * acc[mi][ni][1];
                float h2v = silu_f(acc[mi][ni][2]) * acc[mi][ni][3];
                Hh[(size_t)row * hw + j]     = __float2half(h1v);
                Hh[(size_t)(row+8) * hw + j] = __float2half(h2v);
            } else {
                int col = n0 + n_off + ni*8 + (lane & 3) * 2;
                float2 v0 = { acc[mi][ni][0], acc[mi][ni][1] };
                float2 v1 = { acc[mi][ni][2], acc[mi][ni][3] };
                if (EPI == 1) {
                    float2 a0 = *(const float2*)(addend + (size_t)row * N + col);
                    float2 a1 = *(const float2*)(addend + (size_t)(row + 8) * N + col);
                    v0.x += a0.x; v0.y += a0.y; v1.x += a1.x; v1.y += a1.y;
                }
                *(float2*)(C + (size_t)row * N + col) = v0;
                *(float2*)(C + (size_t)(row + 8) * N + col) = v1;
            }
        }
    }
}

// ---------------- beta/alpha projection v3 -------------------------------------
// Transposed smem weights w16t[16][1024] (lane-consecutive -> conflict-free).
// 256 threads = 8 warps, 32 rows/block, warp-row: coalesced x preload into
// 32 regs, 16 independent accumulators, butterfly reduce, sigmoid, store.
#define BG_SMEM (16*D_*4)   // 65536 B
__global__ __launch_bounds__(256) void bgproj3_k(const float* __restrict__ xn,
                                                 const float* __restrict__ wb,
                                                 const float* __restrict__ wg,
                                                 float* __restrict__ ba)
{
    extern __shared__ float w16t[];   // [16][1024]: rows 0-7 beta, 8-15 alpha
    int tid = threadIdx.x;
    for (int i = tid; i < D_; i += 256) {
        float4 b0 = *(const float4*)(wb + (size_t)i*8);
        float4 b1 = *(const float4*)(wb + (size_t)i*8 + 4);
        float4 g0 = *(const float4*)(wg + (size_t)i*8);
        float4 g1 = *(const float4*)(wg + (size_t)i*8 + 4);
        w16t[0*D_+i]=b0.x;  w16t[1*D_+i]=b0.y;  w16t[2*D_+i]=b0.z;  w16t[3*D_+i]=b0.w;
        w16t[4*D_+i]=b1.x;  w16t[5*D_+i]=b1.y;  w16t[6*D_+i]=b1.z;  w16t[7*D_+i]=b1.w;
        w16t[8*D_+i]=g0.x;  w16t[9*D_+i]=g0.y;  w16t[10*D_+i]=g0.z; w16t[11*D_+i]=g0.w;
        w16t[12*D_+i]=g1.x; w16t[13*D_+i]=g1.y; w16t[14*D_+i]=g1.z; w16t[15*D_+i]=g1.w;
    }
    __syncthreads();

    int warp = tid >> 5, lane = tid & 31;
    int rowbase = blockIdx.x * 32;

    for (int r = warp; r < 32; r += 8) {
        int row = rowbase + r;
        const float* xr = xn + (size_t)row * D_;
        // coalesced preload: lane covers elements i*32+lane
        float xv[32];
        #pragma unroll
        for (int i = 0; i < 32; i++) xv[i] = xr[i*32 + lane];

        float acc[16];
        #pragma unroll
        for (int c = 0; c < 16; c++) acc[c] = 0.f;
        #pragma unroll
        for (int i = 0; i < 32; i++) {
            int e = i*32 + lane;
            #pragma unroll
            for (int c = 0; c < 16; c++)
                acc[c] += xv[i] * w16t[c*D_ + e];
        }
        #pragma unroll
        for (int c = 0; c < 16; c++) {
            float v = acc[c];
            #pragma unroll
            for (int m = 16; m > 0; m >>= 1) v += __shfl_xor_sync(0xffffffffu, v, m);
            if (lane == 0)
                ba[(size_t)row*16 + ((c & 7)*2 + (c >> 3))] = sigmoid_f(v);
        }
    }
}

// ---------------- gated DeltaNet recurrence -----------------------------------
__global__ __launch_bounds__(128) void deltarec_k(const float* __restrict__ qkv,
                                                  const float* __restrict__ ba,
                                                  const float* __restrict__ s0,
                                                  __half* __restrict__ oh,
                                                  float* __restrict__ sout)
{
    int b = blockIdx.z, h = blockIdx.y, chunk = blockIdx.x;
    int tid = threadIdx.x;
    int warp = tid >> 5, lane = tid & 31;
    int grp = lane >> 4;
    int idx = lane & 15;
    int col = chunk*8 + warp*2 + grp;
    int r0  = idx * 8;

    float s[8];
    {
        const float* sp = s0 + (((size_t)(b*H_ + h)*DH_) + r0)*DH_ + col;
        #pragma unroll
        for (int i = 0; i < 8; i++) s[i] = sp[(size_t)i * DH_];
    }

    const float* base = qkv + (size_t)b * T_ * QKV_N + h * DH_;
    const float* qp  = base + r0;
    const float* kp  = base + 1024 + r0;
    const float* vp  = base + 2048 + col;
    const float* bap = ba + ((size_t)b * T_) * (H_*2) + h*2;
    size_t ooff = (size_t)b * T_ * D_ + (size_t)h * DH_ + col;

    float4 k0 = *(const float4*)(kp);
    float4 k1 = *(const float4*)(kp + 4);
    float4 q0 = *(const float4*)(qp);
    float4 q1 = *(const float4*)(qp + 4);
    float vv = *vp;
    float bb = bap[0];
    float aa = bap[1];

    for (int t = 0; t < T_; t++) {
        int tn = (t + 1 < T_) ? t + 1 : t;
        float4 nk0 = *(const float4*)(kp + (size_t)tn*QKV_N);
        float4 nk1 = *(const float4*)(kp + (size_t)tn*QKV_N + 4);
        float4 nq0 = *(const float4*)(qp + (size_t)tn*QKV_N);
        float4 nq1 = *(const float4*)(qp + (size_t)tn*QKV_N + 4);
        float nvv  = vp [(size_t)tn*QKV_N];
        float nbb  = bap[(size_t)tn*16];
        float naa  = bap[(size_t)tn*16 + 1];

        float kr[8] = {k0.x,k0.y,k0.z,k0.w,k1.x,k1.y,k1.z,k1.w};
        float qr[8] = {q0.x,q0.y,q0.z,q0.w,q1.x,q1.y,q1.z,q1.w};

        float pred = 0.f, po = 0.f, qk = 0.f;
        #pragma unroll
        for (int i = 0; i < 8; i++) {
            float sv = s[i] * aa;
            s[i] = sv;
            pred += kr[i] * sv;
            po   += qr[i] * sv;
            qk   += kr[i] * qr[i];
        }
        #pragma unroll
        for (int m = 1; m < 16; m <<= 1) {
            pred += __shfl_xor_sync(0xffffffffu, pred, m);
            po   += __shfl_xor_sync(0xffffffffu, po,   m);
            qk   += __shfl_xor_sync(0xffffffffu, qk,   m);
        }
        float dv = bb * (vv - pred);
        float ov = po + qk * dv;
        #pragma unroll
        for (int i = 0; i < 8; i++) s[i] += kr[i] * dv;

        if (idx == 0) oh[ooff + (size_t)t*D_] = __float2half(ov);

        k0 = nk0; k1 = nk1; q0 = nq0; q1 = nq1;
        vv = nvv; bb = nbb; aa = naa;
    }

    float* sp = sout + (((size_t)(b*H_ + h)*DH_) + r0)*DH_ + col;
    #pragma unroll
    for (int i = 0; i < 8; i++) sp[(size_t)i * DH_] = s[i];
}

// ---------------- launcher -----------------------------------------------------
struct Ptrs {
    float *xn, *qkv, *ba;
    __half *xh, *oh, *hh;
    __half *wqkv, *wo, *wgu, *wd;
    bool init = false;
};
static Ptrs P;

extern "C" void kernel_launch(void* const* d_in, const int* in_sizes, int n_in,
                              void* d_out, int out_size)
{
    const float* x   = (const float*)d_in[0];
    const float* st0 = (const float*)d_in[1];
    const float* wq  = (const float*)d_in[2];
    const float* wk  = (const float*)d_in[3];
    const float* wv  = (const float*)d_in[4];
    const float* wb  = (const float*)d_in[5];
    const float* wg  = (const float*)d_in[6];
    const float* wo  = (const float*)d_in[7];
    const float* wgate = (const float*)d_in[8];
    const float* wup   = (const float*)d_in[9];
    const float* wdown = (const float*)d_in[10];

    float* out = (float*)d_out;   // [x (4194304) | new_state (262144)]
    float* y   = out;
    float* stO = out + X_ELEMS;

    if (!P.init) {
        cudaGetSymbolAddress((void**)&P.xn,  g_xn);
        cudaGetSymbolAddress((void**)&P.qkv, g_qkv);
        cudaGetSymbolAddress((void**)&P.ba,  g_ba);
        cudaGetSymbolAddress((void**)&P.xh,  g_xh);
        cudaGetSymbolAddress((void**)&P.oh,  g_oh);
        cudaGetSymbolAddress((void**)&P.hh,  g_hh);
        cudaGetSymbolAddress((void**)&P.wqkv, g_wqkv);
        cudaGetSymbolAddress((void**)&P.wo,   g_wo);
        cudaGetSymbolAddress((void**)&P.wgu,  g_wgu);
        cudaGetSymbolAddress((void**)&P.wd,   g_wd);
        cudaFuncSetAttribute(hgemm_k<0>, cudaFuncAttributeMaxDynamicSharedMemorySize, HG_SMEM);
        cudaFuncSetAttribute(hgemm_k<1>, cudaFuncAttributeMaxDynamicSharedMemorySize, HG_SMEM);
        cudaFuncSetAttribute(hgemm_k<2>, cudaFuncAttributeMaxDynamicSharedMemorySize, HG_SMEM);
        cudaFuncSetAttribute(bgproj3_k,  cudaFuncAttributeMaxDynamicSharedMemorySize, BG_SMEM);
        P.init = true;
    }

    // [1] merged qkv weight transpose -> fp16 [3072][1024]
    tsplit3_k<<<dim3(D_/32, D_/32, 3), 256>>>(wq, wk, wv, P.wqkv);

    // [2] xn = rmsnorm(x) -> fp16 + fp32 (for bgproj)
    rmsnorm_h_k<<<M_, 256>>>(x, P.xh, P.xn);

    // [3] fused qkv projection   <-- ncu window
    hgemm_k<0><<<dim3(QKV_N/128, M_/128), 128, HG_SMEM>>>(
        P.xh, P.wqkv, nullptr, P.qkv, nullptr, M_, QKV_N, D_);

    // [4] beta/alpha projection (transposed smem weights)
    bgproj3_k<<<M_/32, 256, BG_SMEM>>>(P.xn, wb, wg, P.ba);

    // [5] silu + per-head L2 norm (q,k); silu (v) — fused over qkv
    silul2_qkv_k<<<(M_*24)/8, 256>>>(P.qkv);

    // [6] recurrence -> o (fp16), final state
    deltarec_k<<<dim3(16, H_, B_), 128>>>(P.qkv, P.ba, st0, P.oh, stO);

    // [7] wo transpose; [8] y = x + o @ wo
    tsplit_k<<<dim3(D_/32, D_/32), 256>>>(wo, P.wo, D_, D_, 1, 0);
    hgemm_k<1><<<dim3(D_/128, M_/128), 128, HG_SMEM>>>(
        P.oh, P.wo, x, y, nullptr, M_, D_, D_);

    // [9] yn = rmsnorm(y) -> fp16
    rmsnorm_h_k<<<M_, 256>>>(y, P.xh, nullptr);

    // [10-11] gate/up transposes; [12] fused gate/up GEMM with swiglu epilogue
    tsplit_k<<<dim3(F_/32, D_/32), 256>>>(wgate, P.wgu, D_, F_, 2, 0);
    tsplit_k<<<dim3(F_/32, D_/32), 256>>>(wup,   P.wgu, D_, F_, 2, 1);
    hgemm_k<2><<<dim3(2*F_/128, M_/128), 128, HG_SMEM>>>(
        P.xh, P.wgu, nullptr, nullptr, P.hh, M_, 2*F_, D_);

    // [13] wdown transpose; [14] out = y + h @ w_down
    tsplit_k<<<dim3(D_/32, F_/32), 256>>>(wdown, P.wd, F_, D_, 1, 0);
    hgemm_k<1><<<dim3(D_/128, M_/128), 128, HG_SMEM>>>(
        P.hh, P.wd, y, y, nullptr, M_, D_, F_);
}